// round 14
// baseline (speedup 1.0000x reference)
#include <cuda_runtime.h>
#include <cstdint>
typedef unsigned long long ull;

#define NN 100000
#define NE 1600000
#define DD 128
#define CAP 128                 // adjacency bucket capacity (Poisson(16): overflow ~0)

// -------- scratch (device globals: no allocation allowed) --------
__device__ __align__(256) float g_h[(size_t)NN * DD];     // layer-1 output
__device__ int g_cnt[NN];
__device__ int g_adj[(size_t)NN * CAP];
__device__ int g_is64;

// -------- init: zero counts; warp 0 of block 0 detects edge dtype --------
__global__ void k_init(const unsigned int* __restrict__ e) {
    int i = blockIdx.x * blockDim.x + threadIdx.x;
    if (i < NN) g_cnt[i] = 0;
    if (blockIdx.x == 0 && threadIdx.x < 32) {
        int bad = 0;
        for (int j = threadIdx.x; j < 256; j += 32)
            if (e[2 * j + 1] != 0u) bad = 1;
        unsigned any = __ballot_sync(0xffffffffu, bad);
        if (threadIdx.x == 0) g_is64 = (any == 0u) ? 1 : 0;
    }
}

// -------- fill padded adjacency buckets --------
__global__ void k_fill(const void* __restrict__ edge) {
    int i = blockIdx.x * blockDim.x + threadIdx.x;
    if (i >= NE) return;
    int s, d;
    if (g_is64) {
        const long long* e = (const long long*)edge;
        s = (int)e[i]; d = (int)e[NE + i];
    } else {
        const int* e = (const int*)edge;
        s = e[i]; d = e[NE + i];
    }
    int pos = atomicAdd(&g_cnt[d], 1);
    if (pos < CAP) g_adj[((size_t)d << 7) + pos] = s;
}

// ============ fused SAGE layer: smem gather phase + GEMM phase ============
// out[row,col] = sum_{k<256} A[row,k]*W[col,k]
//   A[:,0:128]   = mean over neighbors of Xin  (phase A -> AGG smem)
//   A[:,128:256] = Xin[row]                    (cp.async chunks 2,3)
//   W[:,0:128]=Wl, W[:,128:256]=Wr             (cp.async streamed per chunk)
#define AGG_STR 132
#define AGG_SZ (128 * AGG_STR)                 // 16896 floats
#define AS_STRIDE 68
#define AS_SZ (128 * AS_STRIDE)                // 8704 floats per X buffer
#define AS_OFF AGG_SZ
#define WS_OFF_F (AGG_SZ + 2 * AS_SZ)          // float offset of W region
#define WSTR 34                                // ull per col (272B, 16B aligned)
#define WBUF (128 * WSTR)                      // ull per W buffer (4352)
#define GSMEM ((WS_OFF_F + 2 * WBUF * 2) * 4)  // 67584+69632+69632 = 206848 B

template <int STRIDE>
__device__ __forceinline__ void mm_chunk(const float* Ab, const ull* Wb,
                                         ull acc[8][8]) {
#pragma unroll 2
    for (int kpl = 0; kpl < 32; kpl++) {
        ull a[8], w[8];
#pragma unroll
        for (int r = 0; r < 8; r++)
            a[r] = *reinterpret_cast<const ull*>(Ab + 4 * r * STRIDE + 2 * kpl);
#pragma unroll
        for (int cc = 0; cc < 8; cc++)
            w[cc] = Wb[cc * 8 * WSTR + kpl];
#pragma unroll
        for (int r = 0; r < 8; r++)
#pragma unroll
            for (int cc = 0; cc < 8; cc++)
                asm("fma.rn.f32x2 %0, %1, %2, %0;"
                    : "+l"(acc[r][cc]) : "l"(a[r]), "l"(w[cc]));
    }
}

__global__ __launch_bounds__(256, 1)
void k_sage(const float* __restrict__ Xin,
            const float* __restrict__ Wl, const float* __restrict__ Wr,
            const float* __restrict__ bias,
            float* __restrict__ out, int do_relu) {
    extern __shared__ float sm[];
    float* AGG = sm;                                     // [128][132]
    float* As = sm + AS_OFF;                             // [2][128][68]
    ull* Ws = reinterpret_cast<ull*>(sm + WS_OFF_F);     // [2][128 col][34]

    int tid = threadIdx.x;
    int row0 = blockIdx.x * 128;
    int wid = tid >> 5, lane = tid & 31;
    int wr = wid & 3, wc = wid >> 2;       // warp tile 4x2 of 32x64
    int lr = lane >> 3, lc = lane & 7;     // lane tile 4x8

    // ---- async producers ----
    int my_r = tid >> 4, my_q = tid & 15;        // X chunk mapping (proven R5)
    auto x_async = [&](int c, int b) {           // c in {2,3}
        int off = (c & 1) * 64;
#pragma unroll
        for (int j = 0; j < 8; j++) {
            int r = my_r + j * 16;
            int row = row0 + r;
            const float* gp = (row < NN) ? (Xin + (size_t)row * DD + off + my_q * 4) : Xin;
            int sz = (row < NN) ? 16 : 0;
            unsigned sa = (unsigned)__cvta_generic_to_shared(
                As + b * AS_SZ + r * AS_STRIDE + my_q * 4);
            asm volatile("cp.async.ca.shared.global [%0], [%1], 16, %2;"
                         :: "r"(sa), "l"(gp), "r"(sz));
        }
    };
    int wcol = tid >> 1, wh = tid & 1;           // W mapping: 2 threads per col
    auto w_async = [&](int c, int b) {           // chunk c: Wl/Wr, k-offset
        const float* WM = (c < 2) ? Wl : Wr;
        const float* src = WM + (size_t)wcol * DD + (c & 1) * 64 + wh * 32;
        float* dst = reinterpret_cast<float*>(Ws + b * WBUF + wcol * WSTR + wh * 16);
#pragma unroll
        for (int t = 0; t < 8; t++) {
            unsigned sa = (unsigned)__cvta_generic_to_shared(dst + t * 4);
            asm volatile("cp.async.ca.shared.global [%0], [%1], 16;"
                         :: "r"(sa), "l"(src + t * 4));
        }
    };

    // g0: W chunk0 -> wb0, X chunk2 -> ab0
    w_async(0, 0);
    x_async(2, 0);
    asm volatile("cp.async.commit_group;");

    // ---- phase A: warp-cooperative gather into AGG smem ----
    {
        const float4* __restrict__ X4 = reinterpret_cast<const float4*>(Xin);
#pragma unroll 1
        for (int i = 0; i < 16; i++) {
            int node = row0 + wid * 16 + i;
            int cnt = (node < NN) ? min(g_cnt[node], CAP) : 0;
            const int* adj = g_adj + ((size_t)node << 7);
            float4 acc = make_float4(0.f, 0.f, 0.f, 0.f);
            for (int j0 = 0; j0 < cnt; j0 += 32) {
                int nb = min(32, cnt - j0);
                int src = (lane < nb) ? adj[j0 + lane] : 0;
#pragma unroll 4
                for (int t = 0; t < nb; t++) {
                    int s = __shfl_sync(0xffffffffu, src, t);
                    float4 v = X4[(size_t)s * 32 + lane];
                    acc.x += v.x; acc.y += v.y; acc.z += v.z; acc.w += v.w;
                }
            }
            float inv = 1.0f / fmaxf((float)cnt, 1.0f);
            acc.x *= inv; acc.y *= inv; acc.z *= inv; acc.w *= inv;
            *reinterpret_cast<float4*>(AGG + (wid * 16 + i) * AGG_STR + lane * 4) = acc;
        }
    }
    asm volatile("cp.async.wait_group 0;");
    __syncthreads();                              // AGG + g0 visible

    ull acc[8][8];
#pragma unroll
    for (int r = 0; r < 8; r++)
#pragma unroll
        for (int c = 0; c < 8; c++) acc[r][c] = 0ull;

    const float* AggB = AGG + (wr * 32 + lr) * AGG_STR;
    const float* AxB0 = As + (wr * 32 + lr) * AS_STRIDE;
    const float* AxB1 = AxB0 + AS_SZ;
    const ull* Wb0 = Ws + (size_t)(wc * 64 + lc) * WSTR;
    const ull* Wb1 = Wb0 + WBUF;

    // g1: W chunk1 -> wb1
    w_async(1, 1);
    asm volatile("cp.async.commit_group;");
    mm_chunk<AGG_STR>(AggB, Wb0, acc);            // chunk 0
    __syncthreads();                              // all done reading wb0
    // g2: W chunk2 -> wb0, X chunk3 -> ab1
    w_async(2, 0);
    x_async(3, 1);
    asm volatile("cp.async.commit_group;");
    asm volatile("cp.async.wait_group 1;");       // g1 done
    __syncthreads();
    mm_chunk<AGG_STR>(AggB + 64, Wb1, acc);       // chunk 1
    __syncthreads();                              // all done reading wb1
    // g3: W chunk3 -> wb1
    w_async(3, 1);
    asm volatile("cp.async.commit_group;");
    asm volatile("cp.async.wait_group 1;");       // g2 done
    __syncthreads();
    mm_chunk<AS_STRIDE>(AxB0, Wb0, acc);          // chunk 2
    asm volatile("cp.async.wait_group 0;");       // g3 done
    __syncthreads();
    mm_chunk<AS_STRIDE>(AxB1, Wb1, acc);          // chunk 3

    // ---- epilogue: combine halves, bias, relu, store ----
#pragma unroll
    for (int r = 0; r < 8; r++) {
        int row = row0 + wr * 32 + lr + 4 * r;
        if (row < NN) {
#pragma unroll
            for (int cc = 0; cc < 8; cc++) {
                int col = wc * 64 + lc + 8 * cc;
                float lo = __uint_as_float((unsigned)(acc[r][cc] & 0xffffffffull));
                float hi = __uint_as_float((unsigned)(acc[r][cc] >> 32));
                float v = lo + hi + bias[col];
                if (do_relu) v = fmaxf(v, 0.f);
                out[(size_t)row * DD + col] = v;
            }
        }
    }
}

extern "C" void kernel_launch(void* const* d_in, const int* in_sizes, int n_in,
                              void* d_out, int out_size) {
    const float* x   = (const float*)d_in[0];
    const void*  edg = d_in[1];
    const float* W1l = (const float*)d_in[2];
    const float* b1  = (const float*)d_in[3];
    const float* W1r = (const float*)d_in[4];
    const float* W2l = (const float*)d_in[5];
    const float* b2  = (const float*)d_in[6];
    const float* W2r = (const float*)d_in[7];
    float* out = (float*)d_out;
    float* g_h_ptr = nullptr;
    cudaGetSymbolAddress((void**)&g_h_ptr, g_h);

    cudaFuncSetAttribute(k_sage, cudaFuncAttributeMaxDynamicSharedMemorySize, GSMEM);

    const int node_blocks = (NN + 255) / 256;        // 391
    const int edge_blocks = (NE + 255) / 256;        // 6250
    const int sage_blocks = (NN + 127) / 128;        // 782

    k_init<<<node_blocks, 256>>>((const unsigned int*)edg);
    k_fill<<<edge_blocks, 256>>>(edg);

    k_sage<<<sage_blocks, 256, GSMEM>>>(x, W1l, W1r, b1, g_h_ptr, /*relu=*/1);
    k_sage<<<sage_blocks, 256, GSMEM>>>(g_h_ptr, W2l, W2r, b2, out, /*relu=*/0);
}

// round 15
// speedup vs baseline: 1.7611x; 1.7611x over previous
#include <cuda_runtime.h>
#include <cstdint>
typedef unsigned long long ull;

#define NN 100000
#define NE 1600000
#define DD 128
#define CAP 128                 // adjacency bucket capacity (Poisson(16): overflow ~0)

// -------- scratch (device globals: no allocation allowed) --------
__device__ __align__(256) float g_agg[(size_t)NN * DD];   // mean-aggregated features
__device__ __align__(256) float g_h[(size_t)NN * DD];     // layer-1 output
__device__ int g_cnt[NN];
__device__ int g_adj[(size_t)NN * CAP];
__device__ int g_is64;

// -------- init: zero counts; warp 0 of block 0 detects edge dtype --------
__global__ void k_init(const unsigned int* __restrict__ e) {
    int i = blockIdx.x * blockDim.x + threadIdx.x;
    if (i < NN) g_cnt[i] = 0;
    if (blockIdx.x == 0 && threadIdx.x < 32) {
        int bad = 0;
        for (int j = threadIdx.x; j < 256; j += 32)
            if (e[2 * j + 1] != 0u) bad = 1;
        unsigned any = __ballot_sync(0xffffffffu, bad);
        if (threadIdx.x == 0) g_is64 = (any == 0u) ? 1 : 0;
    }
}

// -------- fill padded adjacency buckets (2 edges per thread) --------
__global__ void k_fill(const void* __restrict__ edge) {
    int i = (blockIdx.x * blockDim.x + threadIdx.x) * 2;
    if (i >= NE) return;
    int s0, d0, s1, d1;
    if (g_is64) {
        const longlong2* es = (const longlong2*)edge;
        const longlong2* ed = (const longlong2*)((const long long*)edge + NE);
        longlong2 sv = es[i >> 1], dv = ed[i >> 1];
        s0 = (int)sv.x; s1 = (int)sv.y; d0 = (int)dv.x; d1 = (int)dv.y;
    } else {
        const int2* es = (const int2*)edge;
        const int2* ed = (const int2*)((const int*)edge + NE);
        int2 sv = es[i >> 1], dv = ed[i >> 1];
        s0 = sv.x; s1 = sv.y; d0 = dv.x; d1 = dv.y;
    }
    int p0 = atomicAdd(&g_cnt[d0], 1);
    if (p0 < CAP) g_adj[((size_t)d0 << 7) + p0] = s0;
    int p1 = atomicAdd(&g_cnt[d1], 1);
    if (p1 < CAP) g_adj[((size_t)d1 << 7) + p1] = s1;
}

// -------- gather: warp per node, 4 independent accumulators --------
__global__ __launch_bounds__(256)
void k_gather(const float* __restrict__ xext, int use_h) {
    const float4* __restrict__ X4 =
        reinterpret_cast<const float4*>(use_h ? g_h : xext);
    unsigned node = (blockIdx.x * blockDim.x + threadIdx.x) >> 5;
    int lane = threadIdx.x & 31;
    if (node >= NN) return;
    int cnt = min(g_cnt[node], CAP);
    const int* adj = g_adj + ((size_t)node << 7);
    float4 a0 = make_float4(0.f, 0.f, 0.f, 0.f);
    float4 a1 = a0, a2 = a0, a3 = a0;
    for (int j0 = 0; j0 < cnt; j0 += 32) {
        int nb = min(32, cnt - j0);
        int src = (lane < nb) ? adj[j0 + lane] : 0;
        int t = 0;
        for (; t + 4 <= nb; t += 4) {
            int s0 = __shfl_sync(0xffffffffu, src, t);
            int s1 = __shfl_sync(0xffffffffu, src, t + 1);
            int s2 = __shfl_sync(0xffffffffu, src, t + 2);
            int s3 = __shfl_sync(0xffffffffu, src, t + 3);
            float4 v0 = X4[(size_t)s0 * 32 + lane];
            float4 v1 = X4[(size_t)s1 * 32 + lane];
            float4 v2 = X4[(size_t)s2 * 32 + lane];
            float4 v3 = X4[(size_t)s3 * 32 + lane];
            a0.x += v0.x; a0.y += v0.y; a0.z += v0.z; a0.w += v0.w;
            a1.x += v1.x; a1.y += v1.y; a1.z += v1.z; a1.w += v1.w;
            a2.x += v2.x; a2.y += v2.y; a2.z += v2.z; a2.w += v2.w;
            a3.x += v3.x; a3.y += v3.y; a3.z += v3.z; a3.w += v3.w;
        }
        for (; t < nb; t++) {
            int s = __shfl_sync(0xffffffffu, src, t);
            float4 v = X4[(size_t)s * 32 + lane];
            a0.x += v.x; a0.y += v.y; a0.z += v.z; a0.w += v.w;
        }
    }
    a0.x += a1.x; a0.y += a1.y; a0.z += a1.z; a0.w += a1.w;
    a2.x += a3.x; a2.y += a3.y; a2.z += a3.z; a2.w += a3.w;
    a0.x += a2.x; a0.y += a2.y; a0.z += a2.z; a0.w += a2.w;
    float inv = 1.0f / fmaxf((float)cnt, 1.0f);
    a0.x *= inv; a0.y *= inv; a0.z *= inv; a0.w *= inv;
    reinterpret_cast<float4*>(g_agg)[(size_t)node * 32 + lane] = a0;
}

// -------- fused SAGE layer GEMM (proven R5 structure) --------
#define AS_STRIDE 68
#define AS_SZ (128 * AS_STRIDE)
#define WP_STRIDE 130
#define GSMEM (2 * AS_SZ * 4 + 128 * WP_STRIDE * 8)   // 202752 B

__global__ __launch_bounds__(256, 1)
void k_gemm(const float* __restrict__ Xext,
            const float* __restrict__ Wl, const float* __restrict__ Wr,
            const float* __restrict__ bias,
            float* __restrict__ outext,
            int use_h_in, int use_h_out, int do_relu) {
    extern __shared__ float sm[];
    float* As = sm;                                    // [2][128][68]
    ull* Wp = reinterpret_cast<ull*>(sm + 2 * AS_SZ);  // [128 kp][130]
    const float* __restrict__ X = use_h_in ? g_h : Xext;
    float* __restrict__ out = use_h_out ? g_h : outext;

    int tid = threadIdx.x;
    int row0 = blockIdx.x * 128;
    int wid = tid >> 5, lane = tid & 31;
    int wr = wid & 3, wc = wid >> 2;       // warp tile 4x2 of 32x64
    int lr = lane >> 3, lc = lane & 7;     // lane tile 4x8

    // ---- W pair-transposed: Wp[kp][col] = (W[col,2kp], W[col,2kp+1])
    {
        const float2* w0 = (const float2*)Wl;
        const float2* w1 = (const float2*)Wr;
        for (int i = tid; i < 8192; i += 256) {
            int col = i >> 6, kpl = i & 63;
            float2 v0 = w0[col * 64 + kpl];
            float2 v1 = w1[col * 64 + kpl];
            Wp[kpl * WP_STRIDE + col] = *reinterpret_cast<ull*>(&v0);
            Wp[(kpl + 64) * WP_STRIDE + col] = *reinterpret_cast<ull*>(&v1);
        }
    }

    // ---- async A-chunk producer: 8 x cp.async 16B per thread into buffer c&1
    int my_r = tid >> 4, my_q = tid & 15;
    auto async_chunk = [&](int c) {
        const float* P = (c < 2) ? g_agg : X;
        int off = (c & 1) * 64;
        int b = c & 1;
#pragma unroll
        for (int j = 0; j < 8; j++) {
            int r = my_r + j * 16;
            int row = row0 + r;
            const float* gp = (row < NN) ? (P + (size_t)row * DD + off + my_q * 4) : P;
            int sz = (row < NN) ? 16 : 0;
            unsigned sa = (unsigned)__cvta_generic_to_shared(
                As + b * AS_SZ + r * AS_STRIDE + my_q * 4);
            asm volatile("cp.async.ca.shared.global [%0], [%1], 16, %2;"
                         :: "r"(sa), "l"(gp), "r"(sz));
        }
        asm volatile("cp.async.commit_group;");
    };

    ull acc[8][8];
#pragma unroll
    for (int r = 0; r < 8; r++)
#pragma unroll
        for (int c = 0; c < 8; c++) acc[r][c] = 0ull;

    async_chunk(0);
    asm volatile("cp.async.wait_group 0;");
    __syncthreads();

    for (int c = 0; c < 4; c++) {
        if (c < 3) async_chunk(c + 1);                 // overlaps with compute below
        const float* Ab = As + (c & 1) * AS_SZ + (wr * 32 + lr) * AS_STRIDE;
        const ull* Wb = Wp + (c * 32) * WP_STRIDE + wc * 64 + lc;
#pragma unroll 4
        for (int kpl = 0; kpl < 32; kpl++) {
            ull a[8], w[8];
#pragma unroll
            for (int r = 0; r < 8; r++)
                a[r] = *reinterpret_cast<const ull*>(Ab + 4 * r * AS_STRIDE + 2 * kpl);
#pragma unroll
            for (int cc = 0; cc < 8; cc++)
                w[cc] = Wb[kpl * WP_STRIDE + 8 * cc];
#pragma unroll
            for (int r = 0; r < 8; r++)
#pragma unroll
                for (int cc = 0; cc < 8; cc++)
                    asm("fma.rn.f32x2 %0, %1, %2, %0;"
                        : "+l"(acc[r][cc]) : "l"(a[r]), "l"(w[cc]));
        }
        if (c < 3) {
            asm volatile("cp.async.wait_group 0;");
            __syncthreads();
        }
    }

    // ---- epilogue: combine halves, bias, relu, store
#pragma unroll
    for (int r = 0; r < 8; r++) {
        int row = row0 + wr * 32 + lr + 4 * r;
        if (row < NN) {
#pragma unroll
            for (int cc = 0; cc < 8; cc++) {
                int col = wc * 64 + lc + 8 * cc;
                float lo = __uint_as_float((unsigned)(acc[r][cc] & 0xffffffffull));
                float hi = __uint_as_float((unsigned)(acc[r][cc] >> 32));
                float v = lo + hi + bias[col];
                if (do_relu) v = fmaxf(v, 0.f);
                out[(size_t)row * DD + col] = v;
            }
        }
    }
}

extern "C" void kernel_launch(void* const* d_in, const int* in_sizes, int n_in,
                              void* d_out, int out_size) {
    const float* x   = (const float*)d_in[0];
    const void*  edg = d_in[1];
    const float* W1l = (const float*)d_in[2];
    const float* b1  = (const float*)d_in[3];
    const float* W1r = (const float*)d_in[4];
    const float* W2l = (const float*)d_in[5];
    const float* b2  = (const float*)d_in[6];
    const float* W2r = (const float*)d_in[7];
    float* out = (float*)d_out;

    cudaFuncSetAttribute(k_gemm, cudaFuncAttributeMaxDynamicSharedMemorySize, GSMEM);

    const int node_blocks = (NN + 255) / 256;        // 391
    const int fill_blocks = (NE / 2 + 255) / 256;    // 3125
    const int gath_blocks = (NN * 32 + 255) / 256;   // 12500 (warp per node)
    const int gemm_blocks = (NN + 127) / 128;        // 782

    k_init<<<node_blocks, 256>>>((const unsigned int*)edg);
    k_fill<<<fill_blocks, 256>>>(edg);

    // Layer 1
    k_gather<<<gath_blocks, 256>>>(x, /*use_h=*/0);
    k_gemm<<<gemm_blocks, 256, GSMEM>>>(x, W1l, W1r, b1, out,
                                        /*use_h_in=*/0, /*use_h_out=*/1, /*relu=*/1);
    // Layer 2
    k_gather<<<gath_blocks, 256>>>(x, /*use_h=*/1);
    k_gemm<<<gemm_blocks, 256, GSMEM>>>(x, W2l, W2r, b2, out,
                                        /*use_h_in=*/1, /*use_h_out=*/0, /*relu=*/0);
}

// round 16
// speedup vs baseline: 1.7802x; 1.0109x over previous
#include <cuda_runtime.h>
#include <cstdint>
typedef unsigned long long ull;

#define NN 100000
#define NE 1600000
#define DD 128
#define CAP 128

// -------- scratch --------
__device__ __align__(256) float g_agg[(size_t)NN * DD];
__device__ __align__(256) float g_h[(size_t)NN * DD];
__device__ int g_cnt[NN];
__device__ int g_adj[(size_t)NN * CAP];
__device__ int g_is64;
// W tf32 fragment layout: [mat][k8 0..15][ntile 0..15][lane][bh0,bh1,bl0,bl1]
__device__ __align__(256) unsigned g_Wfrag[4 * 32768];

__device__ __forceinline__ unsigned tf32_hi(float x) {
    unsigned h; asm("cvt.rna.tf32.f32 %0, %1;" : "=r"(h) : "f"(x)); return h;
}

// -------- init / fill / wcvt --------
__global__ void k_init(const unsigned int* __restrict__ e) {
    int i = blockIdx.x * blockDim.x + threadIdx.x;
    if (i < NN) g_cnt[i] = 0;
    if (blockIdx.x == 0 && threadIdx.x < 32) {
        int bad = 0;
        for (int j = threadIdx.x; j < 256; j += 32)
            if (e[2 * j + 1] != 0u) bad = 1;
        unsigned any = __ballot_sync(0xffffffffu, bad);
        if (threadIdx.x == 0) g_is64 = (any == 0u) ? 1 : 0;
    }
}

__global__ void k_fill(const void* __restrict__ edge) {
    int i = blockIdx.x * blockDim.x + threadIdx.x;
    if (i >= NE) return;
    int s, d;
    if (g_is64) {
        const long long* e = (const long long*)edge;
        s = (int)e[i]; d = (int)e[NE + i];
    } else {
        const int* e = (const int*)edge;
        s = e[i]; d = e[NE + i];
    }
    int pos = atomicAdd(&g_cnt[d], 1);
    if (pos < CAP) g_adj[((size_t)d << 7) + pos] = s;
}

__global__ void k_wcvt(const float* __restrict__ W1l, const float* __restrict__ W1r,
                       const float* __restrict__ W2l, const float* __restrict__ W2r) {
    int i = blockIdx.x * blockDim.x + threadIdx.x;
    if (i >= 4 * 16384) return;
    int mat = i >> 14, idx = i & 16383;
    int wh = idx & 1, lane = (idx >> 1) & 31, nt = (idx >> 6) & 15, k8 = idx >> 10;
    const float* W = (mat == 0) ? W1l : (mat == 1) ? W1r : (mat == 2) ? W2l : W2r;
    int col = nt * 8 + (lane >> 2);
    int k = k8 * 8 + (lane & 3) + wh * 4;
    float x = W[col * 128 + k];
    unsigned h = tf32_hi(x);
    unsigned l = tf32_hi(x - __uint_as_float(h));
    unsigned base = mat * 32768 + ((k8 * 16 + nt) * 32 + lane) * 4;
    g_Wfrag[base + wh] = h;
    g_Wfrag[base + 2 + wh] = l;
}

// -------- gather: warp per node (exact 506us-build version) --------
__global__ __launch_bounds__(256)
void k_gather(const float* __restrict__ xext, int use_h) {
    const float4* __restrict__ X4 =
        reinterpret_cast<const float4*>(use_h ? g_h : xext);
    unsigned node = (blockIdx.x * blockDim.x + threadIdx.x) >> 5;
    int lane = threadIdx.x & 31;
    if (node >= NN) return;
    int cnt = min(g_cnt[node], CAP);
    const int* adj = g_adj + ((size_t)node << 7);
    float4 acc = make_float4(0.f, 0.f, 0.f, 0.f);
    for (int j0 = 0; j0 < cnt; j0 += 32) {
        int nb = min(32, cnt - j0);
        int src = (lane < nb) ? adj[j0 + lane] : 0;
#pragma unroll 4
        for (int t = 0; t < nb; t++) {
            int s = __shfl_sync(0xffffffffu, src, t);
            float4 v = X4[(size_t)s * 32 + lane];
            acc.x += v.x; acc.y += v.y; acc.z += v.z; acc.w += v.w;
        }
    }
    float inv = 1.0f / fmaxf((float)cnt, 1.0f);
    acc.x *= inv; acc.y *= inv; acc.z *= inv; acc.w *= inv;
    reinterpret_cast<float4*>(g_agg)[(size_t)node * 32 + lane] = acc;
}

// ==================== hybrid dual-pipe GEMM ====================
// grid (2, nRowTiles). blockIdx.x==0: scalar FFMA2, cols 0-63 (R13 path).
//                      blockIdx.x==1: tf32 mma 3-term, cols 64-127 (R10 path).
// scalar smem: As 2x[128][68] f + Ws 2x[64][34] ull = 104448 B
// mma smem:    AH/AL [64 slab][128] f (65536 B) + Wfrag 8192 f (32768 B) = 98304 B
#define AS_STRIDE 68
#define AS_SZ (128 * AS_STRIDE)
#define WSTR 34
#define W_SZ (64 * WSTR)
#define A_LO_F 8192
#define WFRAG_F 16384
#define GSMEM (2 * AS_SZ * 4 + 2 * W_SZ * 8)   // 104448 B (max of both paths)

__device__ __forceinline__ void mma_tf32(float c[4], unsigned a0, unsigned a1,
                                         unsigned a2, unsigned a3,
                                         unsigned b0, unsigned b1) {
    asm volatile(
        "mma.sync.aligned.m16n8k8.row.col.f32.tf32.tf32.f32 "
        "{%0,%1,%2,%3}, {%4,%5,%6,%7}, {%8,%9}, {%0,%1,%2,%3};"
        : "+f"(c[0]), "+f"(c[1]), "+f"(c[2]), "+f"(c[3])
        : "r"(a0), "r"(a1), "r"(a2), "r"(a3), "r"(b0), "r"(b1));
}

__global__ __launch_bounds__(256, 2)
void k_gemm(const float* __restrict__ Xext,
            const float* __restrict__ Wl, const float* __restrict__ Wr,
            const float* __restrict__ bias,
            float* __restrict__ outext,
            int matL, int matR, int use_h_in, int use_h_out, int do_relu) {
    extern __shared__ float sm[];
    const float* __restrict__ X = use_h_in ? g_h : Xext;
    float* __restrict__ out = use_h_out ? g_h : outext;

    int tid = threadIdx.x;
    int row0 = blockIdx.y * 128;
    int wid = tid >> 5, lane = tid & 31;

    if (blockIdx.x == 0) {
        // ================= scalar FFMA2 path, cols 0-63 (R13, verified) =================
        float* As = sm;
        ull* Ws = reinterpret_cast<ull*>(sm + 2 * AS_SZ);
        int wr = wid & 3, wc = wid >> 2;
        int lr = lane >> 3, lc = lane & 7;

        int my_r = tid >> 4, my_q = tid & 15;
        int wcol = tid >> 2, kq = tid & 3;
        auto async_chunk = [&](int c) {
            int b = c & 1;
            const float* P = (c < 2) ? g_agg : X;
            int off = (c & 1) * 64;
#pragma unroll
            for (int j = 0; j < 8; j++) {
                int r = my_r + j * 16;
                int row = row0 + r;
                const float* gp = (row < NN) ? (P + (size_t)row * DD + off + my_q * 4) : P;
                int sz = (row < NN) ? 16 : 0;
                unsigned sa = (unsigned)__cvta_generic_to_shared(
                    As + b * AS_SZ + r * AS_STRIDE + my_q * 4);
                asm volatile("cp.async.ca.shared.global [%0], [%1], 16, %2;"
                             :: "r"(sa), "l"(gp), "r"(sz));
            }
            const float* WM = (c < 2) ? Wl : Wr;
            const float* wsrc = WM + (size_t)wcol * DD + (c & 1) * 64 + kq * 16;
            float* wdst = reinterpret_cast<float*>(Ws + b * W_SZ + wcol * WSTR + kq * 8);
#pragma unroll
            for (int t = 0; t < 4; t++) {
                unsigned sa = (unsigned)__cvta_generic_to_shared(wdst + t * 4);
                asm volatile("cp.async.ca.shared.global [%0], [%1], 16;"
                             :: "r"(sa), "l"(wsrc + t * 4));
            }
            asm volatile("cp.async.commit_group;");
        };

        ull acc[8][4];
#pragma unroll
        for (int r = 0; r < 8; r++)
#pragma unroll
            for (int c = 0; c < 4; c++) acc[r][c] = 0ull;

        async_chunk(0);
        asm volatile("cp.async.wait_group 0;");
        __syncthreads();

        for (int c = 0; c < 4; c++) {
            if (c < 3) async_chunk(c + 1);
            const float* Ab = As + (c & 1) * AS_SZ + (wr * 32 + lr) * AS_STRIDE;
            const ull* Wb = Ws + (c & 1) * W_SZ + (size_t)(wc * 32 + lc) * WSTR;
#pragma unroll 4
            for (int kpl = 0; kpl < 32; kpl++) {
                ull a[8], w[4];
#pragma unroll
                for (int r = 0; r < 8; r++)
                    a[r] = *reinterpret_cast<const ull*>(Ab + 4 * r * AS_STRIDE + 2 * kpl);
#pragma unroll
                for (int cc = 0; cc < 4; cc++)
                    w[cc] = Wb[cc * 8 * WSTR + kpl];
#pragma unroll
                for (int r = 0; r < 8; r++)
#pragma unroll
                    for (int cc = 0; cc < 4; cc++)
                        asm("fma.rn.f32x2 %0, %1, %2, %0;"
                            : "+l"(acc[r][cc]) : "l"(a[r]), "l"(w[cc]));
            }
            if (c < 3) {
                asm volatile("cp.async.wait_group 0;");
                __syncthreads();
            }
        }
#pragma unroll
        for (int r = 0; r < 8; r++) {
            int row = row0 + wr * 32 + lr + 4 * r;
            if (row < NN) {
#pragma unroll
                for (int cc = 0; cc < 4; cc++) {
                    int col = wc * 32 + lc + 8 * cc;
                    float lo = __uint_as_float((unsigned)(acc[r][cc] & 0xffffffffull));
                    float hi = __uint_as_float((unsigned)(acc[r][cc] >> 32));
                    float v = lo + hi + bias[col];
                    if (do_relu) v = fmaxf(v, 0.f);
                    out[(size_t)row * DD + col] = v;
                }
            }
        }
    } else {
        // ================= tf32 mma path, cols 64-127 (R10 mappings) =================
        float* AH = sm;                       // [64 slab][128]
        float* AL = sm + A_LO_F;
        float* WF = sm + WFRAG_F;             // [8 k8][8 nt][lane][4]
        int lq = lane >> 2, lr4 = lane & 3;

        int my_r = tid & 15, my_q = tid >> 4;
        float4 ald[8];
        auto a_ldg = [&](int c) {
            const float* P = (c < 2) ? g_agg : X;
            int koff = (c & 1) * 64;
#pragma unroll
            for (int j = 0; j < 8; j++) {
                int row = row0 + my_r + j * 16;
                ald[j] = (row < NN)
                    ? *reinterpret_cast<const float4*>(P + (size_t)row * DD + koff + my_q * 4)
                    : make_float4(0.f, 0.f, 0.f, 0.f);
            }
        };
        int a_lane = (my_r & 7) * 4;
        int a_word = ((my_r >> 3) & 1) | ((my_q & 1) << 1);
        int a_k8 = my_q >> 1;
        auto a_cvt_sts = [&]() {
#pragma unroll
            for (int j = 0; j < 8; j++) {
                int slab = a_k8 * 8 + j;
                float* ph = AH + (slab * 32 + a_lane) * 4 + a_word;
                float* pl = AL + (slab * 32 + a_lane) * 4 + a_word;
                float xs[4] = {ald[j].x, ald[j].y, ald[j].z, ald[j].w};
#pragma unroll
                for (int t = 0; t < 4; t++) {
                    unsigned h = tf32_hi(xs[t]);
                    ph[t * 4] = __uint_as_float(h);
                    pl[t * 4] = __uint_as_float(tf32_hi(xs[t] - __uint_as_float(h)));
                }
            }
        };
        // W frag producer: nt 8..15 of chunk c; thread copies 32 floats (8x16B)
        auto w_async = [&](int c) {
            int mat = (c < 2) ? matL : matR;
            int k8l = tid >> 5, ntl = (tid & 31) >> 2, inner = (tid & 3) * 32;
            const unsigned* src = g_Wfrag + mat * 32768
                + (((c & 1) * 8 + k8l) * 16 + 8 + ntl) * 128 + inner;
            float* dst = WF + (k8l * 8 + ntl) * 128 + inner;
#pragma unroll
            for (int t = 0; t < 8; t++) {
                unsigned sa = (unsigned)__cvta_generic_to_shared(dst + t * 4);
                asm volatile("cp.async.ca.shared.global [%0], [%1], 16;"
                             :: "r"(sa), "l"(src + t * 4));
            }
            asm volatile("cp.async.commit_group;");
        };

        float C[8][4];
#pragma unroll
        for (int n = 0; n < 8; n++)
#pragma unroll
            for (int t = 0; t < 4; t++) C[n][t] = 0.f;

        a_ldg(0);
        w_async(0);
        a_cvt_sts();
        asm volatile("cp.async.wait_group 0;");
        __syncthreads();

        for (int c = 0; c < 4; c++) {
            if (c < 3) a_ldg(c + 1);
            const float* AHb = AH + (wid * 32 + lane) * 4;
            const float* ALb = AL + (wid * 32 + lane) * 4;
            const float* WBb = WF + lane * 4;
#pragma unroll
            for (int k8 = 0; k8 < 8; k8++) {
                float4 ah = *reinterpret_cast<const float4*>(AHb + k8 * 1024);
                float4 al = *reinterpret_cast<const float4*>(ALb + k8 * 1024);
                unsigned a0 = __float_as_uint(ah.x), a1 = __float_as_uint(ah.y);
                unsigned a2 = __float_as_uint(ah.z), a3 = __float_as_uint(ah.w);
                unsigned l0 = __float_as_uint(al.x), l1 = __float_as_uint(al.y);
                unsigned l2 = __float_as_uint(al.z), l3 = __float_as_uint(al.w);
#pragma unroll
                for (int n = 0; n < 8; n++) {
                    float4 b = *reinterpret_cast<const float4*>(WBb + (k8 * 8 + n) * 128);
                    unsigned bh0 = __float_as_uint(b.x), bh1 = __float_as_uint(b.y);
                    unsigned bl0 = __float_as_uint(b.z), bl1 = __float_as_uint(b.w);
                    mma_tf32(C[n], a0, a1, a2, a3, bh0, bh1);
                    mma_tf32(C[n], a0, a1, a2, a3, bl0, bl1);
                    mma_tf32(C[n], l0, l1, l2, l3, bh0, bh1);
                }
            }
            if (c < 3) {
                __syncthreads();
                a_cvt_sts();
                w_async(c + 1);
                asm volatile("cp.async.wait_group 0;");
                __syncthreads();
            }
        }

        int r0 = row0 + wid * 16 + lq;
#pragma unroll
        for (int n = 0; n < 8; n++) {
            int colb = 64 + n * 8 + 2 * lr4;
            float2 bb = *reinterpret_cast<const float2*>(bias + colb);
            float2 v0 = make_float2(C[n][0] + bb.x, C[n][1] + bb.y);
            float2 v1 = make_float2(C[n][2] + bb.x, C[n][3] + bb.y);
            if (do_relu) {
                v0.x = fmaxf(v0.x, 0.f); v0.y = fmaxf(v0.y, 0.f);
                v1.x = fmaxf(v1.x, 0.f); v1.y = fmaxf(v1.y, 0.f);
            }
            if (r0 < NN)
                *reinterpret_cast<float2*>(out + (size_t)r0 * DD + colb) = v0;
            if (r0 + 8 < NN)
                *reinterpret_cast<float2*>(out + (size_t)(r0 + 8) * DD + colb) = v1;
        }
    }
}

extern "C" void kernel_launch(void* const* d_in, const int* in_sizes, int n_in,
                              void* d_out, int out_size) {
    const float* x   = (const float*)d_in[0];
    const void*  edg = d_in[1];
    const float* W1l = (const float*)d_in[2];
    const float* b1  = (const float*)d_in[3];
    const float* W1r = (const float*)d_in[4];
    const float* W2l = (const float*)d_in[5];
    const float* b2  = (const float*)d_in[6];
    const float* W2r = (const float*)d_in[7];
    float* out = (float*)d_out;

    cudaFuncSetAttribute(k_gemm, cudaFuncAttributeMaxDynamicSharedMemorySize, GSMEM);

    const int node_blocks = (NN + 255) / 256;
    const int edge_blocks = (NE + 255) / 256;
    const int gath_blocks = (NN * 32 + 255) / 256;
    dim3 gemm_grid(2, (NN + 127) / 128);             // method x row-tile (x-fastest)

    k_init<<<node_blocks, 256>>>((const unsigned int*)edg);
    k_fill<<<edge_blocks, 256>>>(edg);
    k_wcvt<<<256, 256>>>(W1l, W1r, W2l, W2r);

    // Layer 1
    k_gather<<<gath_blocks, 256>>>(x, 0);
    k_gemm<<<gemm_grid, 256, GSMEM>>>(x, W1l, W1r, b1, out, 0, 1, 0, 1, 1);
    // Layer 2
    k_gather<<<gath_blocks, 256>>>(x, 1);
    k_gemm<<<gemm_grid, 256, GSMEM>>>(x, W2l, W2r, b2, out, 2, 3, 1, 0, 0);
}